// round 5
// baseline (speedup 1.0000x reference)
#include <cuda_runtime.h>
#include <cuda_bf16.h>
#include <cstdint>

#define BATCH 8
#define HWPX  16384
#define EPSV  1e-5f
#define NCTA  148
#define NTILES 1024   // 128-px tiles

// smem element strides (bf16 elems)
#define STW1 200   // W1s [96][192] pad->200
#define STW2 104   // W2s [192][96] pad->104
#define STX  136   // Xs  [192][128] pad->136
#define STH  136   // Hs  [96][128]  pad->136

// byte offsets in dynamic smem
#define SM_W1 0                       // 96*200*2  = 38400
#define SM_W2 38400                   // 192*104*2 = 39936
#define SM_X  78336                   // 192*136*2 = 52224
#define SM_H  130560                  // 96*136*2  = 26112
#define SM_B1 156672                  // 96*4
#define SM_B2 157056                  // 192*4
#define SM_XG 157824                  // 8*192*4 = 6144
#define DSZ   163968

__device__ __forceinline__ uint32_t smem_u32(const void* p) {
    uint32_t a;
    asm("{ .reg .u64 t; cvta.to.shared.u64 t, %1; cvt.u32.u64 %0, t; }" : "=r"(a) : "l"(p));
    return a;
}
__device__ __forceinline__ void ldsm4(uint32_t (&r)[4], uint32_t addr) {
    asm volatile("ldmatrix.sync.aligned.m8n8.x4.shared.b16 {%0,%1,%2,%3}, [%4];"
                 : "=r"(r[0]), "=r"(r[1]), "=r"(r[2]), "=r"(r[3]) : "r"(addr));
}
__device__ __forceinline__ void ldsm2t(uint32_t (&r)[2], uint32_t addr) {
    asm volatile("ldmatrix.sync.aligned.m8n8.x2.trans.shared.b16 {%0,%1}, [%2];"
                 : "=r"(r[0]), "=r"(r[1]) : "r"(addr));
}
__device__ __forceinline__ void mma16816(float (&d)[4], const uint32_t (&a)[4],
                                         const uint32_t (&b)[2]) {
    asm volatile("mma.sync.aligned.m16n8k16.row.col.f32.bf16.bf16.f32 "
                 "{%0,%1,%2,%3}, {%4,%5,%6,%7}, {%8,%9}, {%0,%1,%2,%3};"
                 : "+f"(d[0]), "+f"(d[1]), "+f"(d[2]), "+f"(d[3])
                 : "r"(a[0]), "r"(a[1]), "r"(a[2]), "r"(a[3]), "r"(b[0]), "r"(b[1]));
}
__device__ __forceinline__ float sigm(float v) {
    return __fdividef(1.f, 1.f + __expf(-v));
}
// exp(s), s in (0,1): e^0.5 * Taylor(u=s-0.5), rel err < 2e-5, FMA-only
__device__ __forceinline__ float exp01(float s) {
    float u = s - 0.5f;
    float p = 8.3333333e-3f;
    p = fmaf(p, u, 4.1666667e-2f);
    p = fmaf(p, u, 0.16666667f);
    p = fmaf(p, u, 0.5f);
    p = fmaf(p, u, 1.0f);
    p = fmaf(p, u, 1.0f);
    return 1.64872127f * p;
}

__device__ float g_gap[BATCH * 192];

// ------------------------- GAP (4 independent accumulators for MLP) -------------------------
__global__ void gap_kernel(const float* __restrict__ x1, const float* __restrict__ x2,
                           const float* __restrict__ x3) {
    int ch = blockIdx.x, b = blockIdx.y;
    const float* x = (ch < 64) ? x1 : (ch < 128) ? x2 : x3;
    const float* p = x + ((size_t)(b * 64 + (ch & 63))) * HWPX;
    int t4 = threadIdx.x * 4;
    float s0 = 0.f, s1 = 0.f, s2 = 0.f, s3 = 0.f;
#pragma unroll
    for (int i = 0; i < 4; i++) {
        float4 a = *(const float4*)(p + t4 + (i * 4 + 0) * 1024);
        float4 c = *(const float4*)(p + t4 + (i * 4 + 1) * 1024);
        float4 d = *(const float4*)(p + t4 + (i * 4 + 2) * 1024);
        float4 e = *(const float4*)(p + t4 + (i * 4 + 3) * 1024);
        s0 += (a.x + a.y) + (a.z + a.w);
        s1 += (c.x + c.y) + (c.z + c.w);
        s2 += (d.x + d.y) + (d.z + d.w);
        s3 += (e.x + e.y) + (e.z + e.w);
    }
    float s = (s0 + s1) + (s2 + s3);
#pragma unroll
    for (int off = 16; off; off >>= 1) s += __shfl_down_sync(0xFFFFFFFFu, s, off);
    __shared__ float sm[8];
    if ((threadIdx.x & 31) == 0) sm[threadIdx.x >> 5] = s;
    __syncthreads();
    if (threadIdx.x == 0) {
        float t = 0.f;
#pragma unroll
        for (int w = 0; w < 8; w++) t += sm[w];
        g_gap[b * 192 + ch] = t * (1.f / (float)HWPX);
    }
}

// ------------------------- fused main kernel -------------------------
__global__ __launch_bounds__(256, 1)
void main_kernel(const float* __restrict__ x1, const float* __restrict__ x2,
                 const float* __restrict__ x3,
                 const float* __restrict__ lw1, const float* __restrict__ lb1,
                 const float* __restrict__ lg1, const float* __restrict__ lbe1,
                 const float* __restrict__ lm1, const float* __restrict__ lv1,
                 const float* __restrict__ lw2, const float* __restrict__ lb2,
                 const float* __restrict__ lg2, const float* __restrict__ lbe2,
                 const float* __restrict__ lm2, const float* __restrict__ lv2,
                 const float* __restrict__ gw1, const float* __restrict__ gb1,
                 const float* __restrict__ gg1, const float* __restrict__ gbe1,
                 const float* __restrict__ gm1, const float* __restrict__ gv1,
                 const float* __restrict__ gw2, const float* __restrict__ gb2,
                 const float* __restrict__ gg2, const float* __restrict__ gbe2,
                 const float* __restrict__ gm2, const float* __restrict__ gv2,
                 float* __restrict__ out) {
    extern __shared__ char dsm[];
    const uint32_t SB = smem_u32(dsm);

    int tid = threadIdx.x;
    int wid = tid >> 5, lane = tid & 31;
    int qrow = lane >> 2;          // 0..7
    int qcol = lane & 3;           // 0..3
    int lsrow = lane & 15;
    int lscol = (lane >> 4) << 3;
    int n0 = wid << 4;             // 16-px strip per warp

    float* B1s = (float*)(dsm + SM_B1);
    float* B2s = (float*)(dsm + SM_B2);
    float* XGs = (float*)(dsm + SM_XG);

    // ---- prologue 1: fold BN into bf16 weights in smem ----
    for (int i = tid; i < 96 * 192; i += 256) {
        int o = i / 192, k = i - o * 192;
        float sc = lg1[o] * rsqrtf(lv1[o] + EPSV);
        *(__nv_bfloat16*)(dsm + SM_W1 + (o * STW1 + k) * 2) = __float2bfloat16_rn(lw1[i] * sc);
        if (k == 0) B1s[o] = fmaf(lb1[o] - lm1[o], sc, lbe1[o]);
    }
    for (int i = tid; i < 192 * 96; i += 256) {
        int o = i / 96, k = i - o * 96;
        float sc = lg2[o] * rsqrtf(lv2[o] + EPSV);
        *(__nv_bfloat16*)(dsm + SM_W2 + (o * STW2 + k) * 2) = __float2bfloat16_rn(lw2[i] * sc);
        if (k == 0) B2s[o] = fmaf(lb2[o] - lm2[o], sc, lbe2[o]);
    }
    __syncthreads();

    // ---- prologue 2: global-branch MLP, warp wid handles batch b=wid ----
    {
        int b = wid;
        float* vb = (float*)(dsm + SM_X) + b * 192;   // scratch (pre-tile)
        float* hb = (float*)(dsm + SM_H) + b * 96;
        for (int i = lane; i < 192; i += 32) vb[i] = g_gap[b * 192 + i];
        __syncwarp();
#pragma unroll
        for (int tt = 0; tt < 3; tt++) {
            int t = lane + 32 * tt;
            float a = gb1[t];
            const float* w = gw1 + t * 192;
#pragma unroll 4
            for (int k = 0; k < 192; k++) a = fmaf(w[k], vb[k], a);
            float s = gg1[t] * rsqrtf(gv1[t] + EPSV);
            hb[t] = fmaxf(fmaf(a - gm1[t], s, gbe1[t]), 0.f);
        }
        __syncwarp();
#pragma unroll
        for (int cc = 0; cc < 6; cc++) {
            int c = lane + 32 * cc;
            float a = gb2[c];
            const float* w = gw2 + c * 96;
#pragma unroll 4
            for (int k = 0; k < 96; k++) a = fmaf(w[k], hb[k], a);
            float s = gg2[c] * rsqrtf(gv2[c] + EPSV);
            XGs[b * 192 + c] = fmaf(a - gm2[c], s, gbe2[c]) + B2s[c];
        }
    }
    __syncthreads();

    const uint32_t W1S = SB + SM_W1, W2S = SB + SM_W2, XS = SB + SM_X, HS = SB + SM_H;

    for (int T = blockIdx.x; T < NTILES; T += NCTA) {
        int b = T >> 7;
        int hw0 = (T & 127) << 7;
        const float* XGb = XGs + b * 192;

        // ---- load X tile [192 ch][128 px] -> bf16 smem ----
#pragma unroll
        for (int j = 0; j < 24; j++) {
            int fidx = (tid + j * 256) * 4;
            int ch = fidx >> 7, px = fidx & 127;
            const float* xp = (ch < 64) ? x1 : (ch < 128) ? x2 : x3;
            float4 v = *(const float4*)(xp + ((size_t)((b << 6) + (ch & 63))) * HWPX + hw0 + px);
            __nv_bfloat162 p0 = __floats2bfloat162_rn(v.x, v.y);
            __nv_bfloat162 p1 = __floats2bfloat162_rn(v.z, v.w);
            *(uint2*)(dsm + SM_X + (ch * STX + px) * 2) =
                make_uint2(*(uint32_t*)&p0, *(uint32_t*)&p1);
        }
        __syncthreads();

        // ---- GEMM1: C1[96ch][16px] per warp, K=192 ----
        uint32_t bfr[12][2][2];
#pragma unroll
        for (int kt = 0; kt < 12; kt++) {
            ldsm2t(bfr[kt][0], XS + ((16 * kt + lsrow) * STX + n0) * 2);
            ldsm2t(bfr[kt][1], XS + ((16 * kt + lsrow) * STX + n0 + 8) * 2);
        }
        float acc1[6][2][4];
#pragma unroll
        for (int mt = 0; mt < 6; mt++) {
#pragma unroll
            for (int nf = 0; nf < 2; nf++)
#pragma unroll
                for (int i = 0; i < 4; i++) acc1[mt][nf][i] = 0.f;
#pragma unroll
            for (int kt = 0; kt < 12; kt++) {
                uint32_t a[4];
                ldsm4(a, W1S + ((16 * mt + lsrow) * STW1 + 16 * kt + lscol) * 2);
                mma16816(acc1[mt][0], a, bfr[kt][0]);
                mma16816(acc1[mt][1], a, bfr[kt][1]);
            }
        }

        // ---- epilogue1: bias + relu -> Hs (own px cols only) ----
#pragma unroll
        for (int mt = 0; mt < 6; mt++) {
            int ca = 16 * mt + qrow;
            float ba = B1s[ca], bb = B1s[ca + 8];
#pragma unroll
            for (int nf = 0; nf < 2; nf++) {
                int pxb = n0 + 8 * nf + 2 * qcol;
                __nv_bfloat162 ha = __floats2bfloat162_rn(fmaxf(acc1[mt][nf][0] + ba, 0.f),
                                                          fmaxf(acc1[mt][nf][1] + ba, 0.f));
                __nv_bfloat162 hb = __floats2bfloat162_rn(fmaxf(acc1[mt][nf][2] + bb, 0.f),
                                                          fmaxf(acc1[mt][nf][3] + bb, 0.f));
                *(uint32_t*)(dsm + SM_H + (ca * STH + pxb) * 2) = *(uint32_t*)&ha;
                *(uint32_t*)(dsm + SM_H + ((ca + 8) * STH + pxb) * 2) = *(uint32_t*)&hb;
            }
        }
        __syncwarp();

        // ---- GEMM2: C2[192ch][16px] per warp, K=96 ----
        uint32_t hfr[6][2][2];
#pragma unroll
        for (int kt = 0; kt < 6; kt++) {
            ldsm2t(hfr[kt][0], HS + ((16 * kt + lsrow) * STH + n0) * 2);
            ldsm2t(hfr[kt][1], HS + ((16 * kt + lsrow) * STH + n0 + 8) * 2);
        }
        float acc2[12][2][4];
#pragma unroll
        for (int mt = 0; mt < 12; mt++) {
#pragma unroll
            for (int nf = 0; nf < 2; nf++)
#pragma unroll
                for (int i = 0; i < 4; i++) acc2[mt][nf][i] = 0.f;
#pragma unroll
            for (int kt = 0; kt < 6; kt++) {
                uint32_t a[4];
                ldsm4(a, W2S + ((16 * mt + lsrow) * STW2 + 16 * kt + lscol) * 2);
                mma16816(acc2[mt][0], a, hfr[kt][0]);
                mma16816(acc2[mt][1], a, hfr[kt][1]);
            }
        }

        // ---- epilogue2: sigmoid -> softmax over {c,c+64,c+128} -> weighted sum ----
#pragma unroll
        for (int mt = 0; mt < 4; mt++) {
#pragma unroll
            for (int j = 0; j < 2; j++) {
                int c = 16 * mt + 8 * j + qrow;
                float l0 = XGb[c], l1 = XGb[c + 64], l2 = XGb[c + 128];
                const float* p0 = x1 + ((size_t)((b << 6) + c)) * HWPX + hw0;
                const float* p1 = x2 + ((size_t)((b << 6) + c)) * HWPX + hw0;
                const float* p2 = x3 + ((size_t)((b << 6) + c)) * HWPX + hw0;
                float* po = out + ((size_t)((b << 6) + c)) * HWPX + hw0;
#pragma unroll
                for (int nf = 0; nf < 2; nf++) {
                    int pxb = n0 + 8 * nf + 2 * qcol;
                    float e00 = exp01(sigm(acc2[mt][nf][2 * j] + l0));
                    float e01 = exp01(sigm(acc2[mt][nf][2 * j + 1] + l0));
                    float e10 = exp01(sigm(acc2[mt + 4][nf][2 * j] + l1));
                    float e11 = exp01(sigm(acc2[mt + 4][nf][2 * j + 1] + l1));
                    float e20 = exp01(sigm(acc2[mt + 8][nf][2 * j] + l2));
                    float e21 = exp01(sigm(acc2[mt + 8][nf][2 * j + 1] + l2));
                    float2 xa = *(const float2*)(p0 + pxb);
                    float2 xb = *(const float2*)(p1 + pxb);
                    float2 xc = *(const float2*)(p2 + pxb);
                    float i0 = __fdividef(1.f, e00 + e10 + e20);
                    float i1 = __fdividef(1.f, e01 + e11 + e21);
                    float2 r;
                    r.x = (e00 * xa.x + e10 * xb.x + e20 * xc.x) * i0;
                    r.y = (e01 * xa.y + e11 * xb.y + e21 * xc.y) * i1;
                    *(float2*)(po + pxb) = r;
                }
            }
        }
        __syncthreads();
    }
}

extern "C" void kernel_launch(void* const* d_in, const int* in_sizes, int n_in,
                              void* d_out, int out_size) {
    const float* x1 = (const float*)d_in[0];
    const float* x2 = (const float*)d_in[1];
    const float* x3 = (const float*)d_in[2];
    const float* lw1 = (const float*)d_in[3];
    const float* lb1 = (const float*)d_in[4];
    const float* lg1 = (const float*)d_in[5];
    const float* lbe1 = (const float*)d_in[6];
    const float* lm1 = (const float*)d_in[7];
    const float* lv1 = (const float*)d_in[8];
    const float* lw2 = (const float*)d_in[9];
    const float* lb2 = (const float*)d_in[10];
    const float* lg2 = (const float*)d_in[11];
    const float* lbe2 = (const float*)d_in[12];
    const float* lm2 = (const float*)d_in[13];
    const float* lv2 = (const float*)d_in[14];
    const float* gw1 = (const float*)d_in[15];
    const float* gb1 = (const float*)d_in[16];
    const float* gg1 = (const float*)d_in[17];
    const float* gbe1 = (const float*)d_in[18];
    const float* gm1 = (const float*)d_in[19];
    const float* gv1 = (const float*)d_in[20];
    const float* gw2 = (const float*)d_in[21];
    const float* gb2 = (const float*)d_in[22];
    const float* gg2 = (const float*)d_in[23];
    const float* gbe2 = (const float*)d_in[24];
    const float* gm2 = (const float*)d_in[25];
    const float* gv2 = (const float*)d_in[26];
    float* out = (float*)d_out;

    cudaFuncSetAttribute(main_kernel, cudaFuncAttributeMaxDynamicSharedMemorySize, DSZ);

    gap_kernel<<<dim3(192, BATCH), 256>>>(x1, x2, x3);
    main_kernel<<<NCTA, 256, DSZ>>>(x1, x2, x3,
                                    lw1, lb1, lg1, lbe1, lm1, lv1,
                                    lw2, lb2, lg2, lbe2, lm2, lv2,
                                    gw1, gb1, gg1, gbe1, gm1, gv1,
                                    gw2, gb2, gg2, gbe2, gm2, gv2, out);
}